// round 14
// baseline (speedup 1.0000x reference)
#include <cuda_runtime.h>
#include <cuda_bf16.h>
#include <cstdint>
#include <math.h>

// Problem dims (fixed)
#define B_SZ   4
#define S_LEN  2048
#define D_DIM  1024
#define NHEAD  16
#define DFF_D  4096
#define M_ROWS 8192   // B*S
#define LOG2E  1.4426950408889634f

// ---------------- scratch (static __device__; no allocation) --------------
__device__ __nv_bfloat16 g_xhi [M_ROWS * D_DIM], g_xlo [M_ROWS * D_DIM];
__device__ __nv_bfloat16 g_wqkvhi[3 * D_DIM * D_DIM], g_wqkvlo[3 * D_DIM * D_DIM];
__device__ __nv_bfloat16 g_wohi[D_DIM * D_DIM], g_wolo[D_DIM * D_DIM];
__device__ __nv_bfloat16 g_w1hi[DFF_D * D_DIM], g_w1lo[DFF_D * D_DIM];
__device__ __nv_bfloat16 g_w2hi[D_DIM * DFF_D], g_w2lo[D_DIM * DFF_D];
__device__ float         g_bqkv[3 * D_DIM];
__device__ __nv_bfloat16 g_qkvhi[(size_t)M_ROWS * 3 * D_DIM], g_qkvlo[(size_t)M_ROWS * 3 * D_DIM];
__device__ __nv_bfloat16 g_ctxhi[M_ROWS * D_DIM], g_ctxlo[M_ROWS * D_DIM];
__device__ float         g_y1 [M_ROWS * D_DIM], g_x1f[M_ROWS * D_DIM], g_y2[M_ROWS * D_DIM];
__device__ __nv_bfloat16 g_x1hi[M_ROWS * D_DIM], g_x1lo[M_ROWS * D_DIM];
__device__ __nv_bfloat16 g_hhi[(size_t)M_ROWS * DFF_D], g_hlo[(size_t)M_ROWS * DFF_D];

// ======================= helpers ==========================================
__device__ __forceinline__ uint32_t smem_u32(const void* p) {
    uint32_t a;
    asm("{ .reg .u64 t; cvta.to.shared.u64 t, %1; cvt.u32.u64 %0, t; }" : "=r"(a) : "l"(p));
    return a;
}
__device__ __forceinline__ uint32_t sw128(uint32_t off) { return off ^ ((off >> 3) & 0x70); }
__device__ __forceinline__ uint32_t sw64 (uint32_t off) { return off ^ ((off >> 3) & 0x30); }

__device__ __forceinline__ void ldsm_x4(uint32_t& r0, uint32_t& r1, uint32_t& r2, uint32_t& r3,
                                        uint32_t addr) {
    asm volatile("ldmatrix.sync.aligned.m8n8.x4.shared.b16 {%0,%1,%2,%3}, [%4];"
                 : "=r"(r0), "=r"(r1), "=r"(r2), "=r"(r3) : "r"(addr));
}
__device__ __forceinline__ void ldsm_x4_t(uint32_t& r0, uint32_t& r1, uint32_t& r2, uint32_t& r3,
                                          uint32_t addr) {
    asm volatile("ldmatrix.sync.aligned.m8n8.x4.trans.shared.b16 {%0,%1,%2,%3}, [%4];"
                 : "=r"(r0), "=r"(r1), "=r"(r2), "=r"(r3) : "r"(addr));
}
__device__ __forceinline__ void mma_bf16(float* d, uint32_t a0, uint32_t a1, uint32_t a2,
                                         uint32_t a3, uint32_t b0, uint32_t b1) {
    asm volatile(
        "mma.sync.aligned.m16n8k16.row.col.f32.bf16.bf16.f32 "
        "{%0,%1,%2,%3}, {%4,%5,%6,%7}, {%8,%9}, {%0,%1,%2,%3};"
        : "+f"(d[0]), "+f"(d[1]), "+f"(d[2]), "+f"(d[3])
        : "r"(a0), "r"(a1), "r"(a2), "r"(a3), "r"(b0), "r"(b1));
}
// split pair (a=elem0/lo, b=elem1/hi) into hi/lo bf16x2
__device__ __forceinline__ void split2(float a, float b, uint32_t& hi, uint32_t& lo) {
    uint32_t h;
    asm("cvt.rn.bf16x2.f32 %0, %1, %2;" : "=r"(h) : "f"(b), "f"(a));
    float ra = a - __uint_as_float(h << 16);
    float rb = b - __uint_as_float(h & 0xffff0000u);
    uint32_t l;
    asm("cvt.rn.bf16x2.f32 %0, %1, %2;" : "=r"(l) : "f"(rb), "f"(ra));
    hi = h; lo = l;
}
__device__ __forceinline__ float ex2(float x) {
    float r;
    asm("ex2.approx.ftz.f32 %0, %1;" : "=f"(r) : "f"(x));
    return r;
}

#define CP_ASYNC16(dst, src) \
    asm volatile("cp.async.cg.shared.global [%0], [%1], 16;" :: "r"(dst), "l"(src))
#define CP_COMMIT asm volatile("cp.async.commit_group;" ::: "memory")
#define CP_WAIT1  asm volatile("cp.async.wait_group 1;" ::: "memory")
#define CP_WAIT0  asm volatile("cp.async.wait_group 0;" ::: "memory")

// ---------------- fused fp32 -> split bf16 conversion + bias concat -------
// blockIdx.y 0..6: split segments; blockIdx.y 7: bias concat (fp32).
__global__ void convsplit8(
    const float* s0, __nv_bfloat16* h0, __nv_bfloat16* l0, int n0,
    const float* s1, __nv_bfloat16* h1, __nv_bfloat16* l1, int n1,
    const float* s2, __nv_bfloat16* h2, __nv_bfloat16* l2, int n2,
    const float* s3, __nv_bfloat16* h3, __nv_bfloat16* l3, int n3,
    const float* s4, __nv_bfloat16* h4, __nv_bfloat16* l4, int n4,
    const float* s5, __nv_bfloat16* h5, __nv_bfloat16* l5, int n5,
    const float* s6, __nv_bfloat16* h6, __nv_bfloat16* l6, int n6,
    const float* bq, const float* bk, const float* bv, float* bqkv)
{
    if (blockIdx.y == 7) {
        const int stride = gridDim.x * blockDim.x;
        for (int i = blockIdx.x * blockDim.x + threadIdx.x; i < 3 * D_DIM; i += stride)
            bqkv[i] = (i < D_DIM) ? bq[i]
                    : ((i < 2 * D_DIM) ? bk[i - D_DIM] : bv[i - 2 * D_DIM]);
        return;
    }
    const float* src; __nv_bfloat16 *hi, *lo; int n;
    switch (blockIdx.y) {
        case 0: src = s0; hi = h0; lo = l0; n = n0; break;
        case 1: src = s1; hi = h1; lo = l1; n = n1; break;
        case 2: src = s2; hi = h2; lo = l2; n = n2; break;
        case 3: src = s3; hi = h3; lo = l3; n = n3; break;
        case 4: src = s4; hi = h4; lo = l4; n = n4; break;
        case 5: src = s5; hi = h5; lo = l5; n = n5; break;
        default: src = s6; hi = h6; lo = l6; n = n6; break;
    }
    const int stride = gridDim.x * blockDim.x;
    for (int i = blockIdx.x * blockDim.x + threadIdx.x; i < n; i += stride) {
        float4 v = ((const float4*)src)[i];
        uint32_t a0, b0, a1, b1;
        split2(v.x, v.y, a0, b0);
        split2(v.z, v.w, a1, b1);
        ((uint2*)hi)[i] = make_uint2(a0, a1);
        ((uint2*)lo)[i] = make_uint2(b0, b1);
    }
}

// ========== HMMA GEMM on pre-split inputs: C = A @ B^T + bias =============
// Tile 128x128, K-chunk 32 (64B SW64 rows), 3-stage cp.async, one sync per
// chunk, 2 CTAs/SM. Inner loop: B-group pairs, 3 passes of 8 independent
// MMAs (RAW distance 8). MODE 0: fp32 out (+RES). MODE 1: split bf16 (+RELU).
#define ST_A  0
#define ST_AL 8192
#define ST_B  16384
#define ST_BL 24576
#define ST_SZ 32768
#define GEMM_SMEM (3 * ST_SZ)

template<int MODE, bool RELU, bool RES>
__global__ __launch_bounds__(256, 2)
void hmma_gemm2(const __nv_bfloat16* __restrict__ Ahi, const __nv_bfloat16* __restrict__ Alo,
                const __nv_bfloat16* __restrict__ Bhi, const __nv_bfloat16* __restrict__ Blo,
                const float* __restrict__ bias, const float* __restrict__ Rp,
                float* __restrict__ Cf, __nv_bfloat16* __restrict__ Chi,
                __nv_bfloat16* __restrict__ Clo, int M, int N, int K)
{
    extern __shared__ __align__(1024) char smem[];
    const uint32_t sb = smem_u32(smem);
    const int tid  = threadIdx.x;
    const int lane = tid & 31;
    const int wid  = tid >> 5;
    const int wm   = wid & 3;
    const int wn   = wid >> 2;
    const int bx = blockIdx.x, by = blockIdx.y;

    const int lrow = tid >> 1;
    const int lc   = (tid & 1) * 2;
    const __nv_bfloat16* src0 = Ahi + (size_t)(by * 128 + lrow) * K;
    const __nv_bfloat16* src1 = Alo + (size_t)(by * 128 + lrow) * K;
    const __nv_bfloat16* src2 = Bhi + (size_t)(bx * 128 + lrow) * K;
    const __nv_bfloat16* src3 = Blo + (size_t)(bx * 128 + lrow) * K;
    uint32_t dsw[2];
#pragma unroll
    for (int ch = 0; ch < 2; ch++) dsw[ch] = sw64((uint32_t)(lrow * 64 + (lc + ch) * 16));

    const int nchunk = K >> 5;
    auto issue = [&](int c) {
        const uint32_t stg = sb + (uint32_t)(c % 3) * ST_SZ;
        const int ko = c * 32 + lc * 8;
#pragma unroll
        for (int ch = 0; ch < 2; ch++) {
            CP_ASYNC16(stg + ST_A  + dsw[ch], src0 + ko + ch * 8);
            CP_ASYNC16(stg + ST_AL + dsw[ch], src1 + ko + ch * 8);
            CP_ASYNC16(stg + ST_B  + dsw[ch], src2 + ko + ch * 8);
            CP_ASYNC16(stg + ST_BL + dsw[ch], src3 + ko + ch * 8);
        }
        CP_COMMIT;
    };

    uint32_t aoff[2];
    {
        const int m  = wm * 32 + (lane & 7) + 8 * ((lane >> 3) & 1);
        const int ak = (lane >> 4) * 16;
        aoff[0] = (uint32_t)(m * 64 + ak);
        aoff[1] = aoff[0] + 16 * 64;
    }
    uint32_t boff[4];
    {
        const int bk = ((lane >> 3) & 1) * 16;
#pragma unroll
        for (int jg = 0; jg < 4; jg++) {
            const int n = wn * 64 + jg * 16 + (lane & 7) + 8 * (lane >> 4);
            boff[jg] = (uint32_t)(n * 64 + bk);
        }
    }

    float acc[2][8][4];
#pragma unroll
    for (int i = 0; i < 2; i++)
#pragma unroll
        for (int j = 0; j < 8; j++)
#pragma unroll
            for (int r = 0; r < 4; r++) acc[i][j][r] = 0.f;

    issue(0);
    issue(1);

    for (int c = 0; c < nchunk; c++) {
        if (c == nchunk - 1) { CP_WAIT0; } else { CP_WAIT1; }
        __syncthreads();
        if (c + 2 < nchunk) issue(c + 2);
        const uint32_t bufb = sb + (uint32_t)(c % 3) * ST_SZ;
#pragma unroll
        for (int ks = 0; ks < 2; ks++) {
            const uint32_t o = ks * 32;
            uint32_t ah0[4], ah1[4], al0[4], al1[4];
            ldsm_x4(ah0[0], ah0[1], ah0[2], ah0[3], bufb + ST_A  + sw64(aoff[0] + o));
            ldsm_x4(ah1[0], ah1[1], ah1[2], ah1[3], bufb + ST_A  + sw64(aoff[1] + o));
            ldsm_x4(al0[0], al0[1], al0[2], al0[3], bufb + ST_AL + sw64(aoff[0] + o));
            ldsm_x4(al1[0], al1[1], al1[2], al1[3], bufb + ST_AL + sw64(aoff[1] + o));
#pragma unroll
            for (int jp = 0; jp < 2; jp++) {
                uint32_t b0h[4], b0l[4], b1h[4], b1l[4];
                ldsm_x4(b0h[0], b0h[1], b0h[2], b0h[3], bufb + ST_B  + sw64(boff[2 * jp]     + o));
                ldsm_x4(b1h[0], b1h[1], b1h[2], b1h[3], bufb + ST_B  + sw64(boff[2 * jp + 1] + o));
                ldsm_x4(b0l[0], b0l[1], b0l[2], b0l[3], bufb + ST_BL + sw64(boff[2 * jp]     + o));
                ldsm_x4(b1l[0], b1l[1], b1l[2], b1l[3], bufb + ST_BL + sw64(boff[2 * jp + 1] + o));
                const int j0 = 4 * jp, j1 = j0 + 1, j2 = j0 + 2, j3 = j0 + 3;
                // pass 1: hi*hi — 8 independent MMAs
                mma_bf16(acc[0][j0], ah0[0], ah0[1], ah0[2], ah0[3], b0h[0], b0h[1]);
                mma_bf16(acc[0][j1], ah0[0], ah0[1], ah0[2], ah0[3], b0h[2], b0h[3]);
                mma_bf16(acc[0][j2], ah0[0], ah0[1], ah0[2], ah0[3], b1h[0], b1h[1]);
                mma_bf16(acc[0][j3], ah0[0], ah0[1], ah0[2], ah0[3], b1h[2], b1h[3]);
                mma_bf16(acc[1][j0], ah1[0], ah1[1], ah1[2], ah1[3], b0h[0], b0h[1]);
                mma_bf16(acc[1][j1], ah1[0], ah1[1], ah1[2], ah1[3], b0h[2], b0h[3]);
                mma_bf16(acc[1][j2], ah1[0], ah1[1], ah1[2], ah1[3], b1h[0], b1h[1]);
                mma_bf16(acc[1][j3], ah1[0], ah1[1], ah1[2], ah1[3], b1h[2], b1h[3]);
                // pass 2: hi*lo — 8 independent MMAs (RAW distance 8)
                mma_bf16(acc[0][j0], ah0[0], ah0[1], ah0[2], ah0[3], b0l[0], b0l[1]);
                mma_bf16(acc[0][j1], ah0[0], ah0[1], ah0[2], ah0[3], b0l[2], b0l[3]);
                mma_bf16(acc[0][j2], ah0[0], ah0[1], ah0[2], ah0[3], b1l[0], b1l[1]);
                mma_bf16(acc[0][j3], ah0[0], ah0[1], ah0[2], ah0[3], b1l[2], b1l[3]);
                mma_bf16(acc[1][j0], ah1[0], ah1[1], ah1[2], ah1[3], b0l[0], b0l[1]);
                mma_bf16(acc[1][j1], ah1[0], ah1[1], ah1[2], ah1[3], b0l[2], b0l[3]);
                mma_bf16(acc[1][j2], ah1[0], ah1[1], ah1[2], ah1[3], b1l[0], b1l[1]);
                mma_bf16(acc[1][j3], ah1[0], ah1[1], ah1[2], ah1[3], b1l[2], b1l[3]);
                // pass 3: lo*hi — 8 independent MMAs
                mma_bf16(acc[0][j0], al0[0], al0[1], al0[2], al0[3], b0h[0], b0h[1]);
                mma_bf16(acc[0][j1], al0[0], al0[1], al0[2], al0[3], b0h[2], b0h[3]);
                mma_bf16(acc[0][j2], al0[0], al0[1], al0[2], al0[3], b1h[0], b1h[1]);
                mma_bf16(acc[0][j3], al0[0], al0[1], al0[2], al0[3], b1h[2], b1h[3]);
                mma_bf16(acc[1][j0], al1[0], al1[1], al1[2], al1[3], b0h[0], b0h[1]);
                mma_bf16(acc[1][j1], al1[0], al1[1], al1[2], al1[3], b0h[2], b0h[3]);
                mma_bf16(acc[1][j2], al1[0], al1[1], al1[2], al1[3], b1h[0], b1h[1]);
                mma_bf16(acc[1][j3], al1[0], al1[1], al1[2], al1[3], b1h[2], b1h[3]);
            }
        }
    }

    // epilogue: fragment row = lane>>2 (+8), col = (lane&3)*2
    const int rbase = by * 128 + wm * 32 + (lane >> 2);
    const int cbase = bx * 128 + wn * 64 + (lane & 3) * 2;
#pragma unroll
    for (int i = 0; i < 2; i++) {
#pragma unroll
        for (int j = 0; j < 8; j++) {
            const int r0 = rbase + i * 16;
            const int cc = cbase + j * 8;
            const float2 bv = *(const float2*)&bias[cc];
            float2 v0, v1;
            v0.x = acc[i][j][0] + bv.x;  v0.y = acc[i][j][1] + bv.y;
            v1.x = acc[i][j][2] + bv.x;  v1.y = acc[i][j][3] + bv.y;
            if (RES) {
                float2 q0 = *(const float2*)&Rp[(size_t)r0 * N + cc];
                float2 q1 = *(const float2*)&Rp[(size_t)(r0 + 8) * N + cc];
                v0.x += q0.x; v0.y += q0.y; v1.x += q1.x; v1.y += q1.y;
            }
            if (RELU) {
                v0.x = fmaxf(v0.x, 0.f); v0.y = fmaxf(v0.y, 0.f);
                v1.x = fmaxf(v1.x, 0.f); v1.y = fmaxf(v1.y, 0.f);
            }
            if (MODE == 0) {
                *(float2*)&Cf[(size_t)r0 * N + cc]       = v0;
                *(float2*)&Cf[(size_t)(r0 + 8) * N + cc] = v1;
            } else {
                uint32_t h, l;
                split2(v0.x, v0.y, h, l);
                *(uint32_t*)(Chi + (size_t)r0 * N + cc) = h;
                *(uint32_t*)(Clo + (size_t)r0 * N + cc) = l;
                split2(v1.x, v1.y, h, l);
                *(uint32_t*)(Chi + (size_t)(r0 + 8) * N + cc) = h;
                *(uint32_t*)(Clo + (size_t)(r0 + 8) * N + cc) = l;
            }
        }
    }
}

// ---------------- HMMA flash attention (64q, 128 threads, 3 CTA/SM) ------
// V consumed straight from qkv layout [key, d] via ldmatrix.trans (no vtrans).
// Q staging region is overlapped by the K/V stage buffers.
#define AT_STSZ  32768        // KHI 8K | KLO 8K | VHI 8K | VLO 8K
#define AT_MASK  (2 * AT_STSZ)
#define AT_SMEM  (AT_MASK + 2 * 256 + 256)

__global__ __launch_bounds__(128, 3)
void attn_mma(const __nv_bfloat16* __restrict__ qkvhi, const __nv_bfloat16* __restrict__ qkvlo,
              const int* __restrict__ mask,
              __nv_bfloat16* __restrict__ ctxhi, __nv_bfloat16* __restrict__ ctxlo)
{
    extern __shared__ __align__(1024) char smem[];
    const uint32_t sb = smem_u32(smem);
    const int tid  = threadIdx.x;
    const int lane = tid & 31;
    const int wid  = tid >> 5;
    const int q0   = blockIdx.x * 64;
    const int bh   = blockIdx.y;
    const int b    = bh >> 4, h = bh & 15;

    // ---- load Q tile (hi at 0, lo at 8192) into smem (overlaps stage 0) ----
#pragma unroll
    for (int it = 0; it < 4; it++) {
        const int idx = it * 128 + tid;
        const int row = idx >> 3, ch = idx & 7;
        const size_t src = (size_t)(b * S_LEN + q0 + row) * 3072 + h * 64 + ch * 8;
        const uint32_t d = sw128((uint32_t)(row * 128 + ch * 16));
        *(uint4*)(smem + d)        = *(const uint4*)(qkvhi + src);
        *(uint4*)(smem + 8192 + d) = *(const uint4*)(qkvlo + src);
    }

    // ldmatrix offset bases
    uint32_t qoffb;
    {
        const int m  = wid * 16 + (lane & 7) + 8 * ((lane >> 3) & 1);
        const int ak = (lane >> 4) * 16;
        qoffb = (uint32_t)(m * 128 + ak);
    }
    uint32_t boffA[4];     // K fragments (non-trans): rows=n(keys), cols=k bytes
    {
        const int bk = ((lane >> 3) & 1) * 16;
#pragma unroll
        for (int jg = 0; jg < 4; jg++) {
            const int n = jg * 16 + (lane & 7) + 8 * (lane >> 4);
            boffA[jg] = (uint32_t)(n * 128 + bk);
        }
    }
    // V trans-fragment base: rows=k(keys), cols=n(d) bytes
    const uint32_t vbase = (uint32_t)(((lane & 7) + 8 * ((lane >> 3) & 1)) * 128
                                      + (lane >> 4) * 16);

    __syncthreads();   // Q smem visible
    uint32_t qh[4][4], ql[4][4];
#pragma unroll
    for (int ks = 0; ks < 4; ks++) {
        ldsm_x4(qh[ks][0], qh[ks][1], qh[ks][2], qh[ks][3], sb +        sw128(qoffb + ks * 32));
        ldsm_x4(ql[ks][0], ql[ks][1], ql[ks][2], ql[ks][3], sb + 8192 + sw128(qoffb + ks * 32));
    }
    __syncthreads();   // all warps done reading Q before stages overwrite it

    auto issue = [&](int t) {
        const uint32_t stg = sb + (t & 1) * AT_STSZ;
        const int kt = t * 64;
#pragma unroll
        for (int it = 0; it < 4; it++) {
            const int idx = it * 128 + tid;
            const int row = idx >> 3, ch = idx & 7;
            const uint32_t d = sw128((uint32_t)(row * 128 + ch * 16));
            const size_t ksrc = (size_t)(b * S_LEN + kt + row) * 3072 + 1024 + h * 64 + ch * 8;
            CP_ASYNC16(stg +         d, qkvhi + ksrc);
            CP_ASYNC16(stg +  8192 + d, qkvlo + ksrc);
            CP_ASYNC16(stg + 16384 + d, qkvhi + ksrc + 1024);   // V cols [2048..3072)
            CP_ASYNC16(stg + 24576 + d, qkvlo + ksrc + 1024);
        }
        CP_COMMIT;
        if (tid < 64) {
            float* mp = (float*)(smem + AT_MASK + (t & 1) * 256);
            mp[tid] = mask[b * S_LEN + kt + tid] ? 0.f : -1e9f;
        }
    };

    issue(0);
    issue(1);

    float o[8][4];
#pragma unroll
    for (int j = 0; j < 8; j++)
#pragma unroll
        for (int r = 0; r < 4; r++) o[j][r] = 0.f;
    float m0 = -1e30f, m1 = -1e30f, l0 = 0.f, l1 = 0.f;
    const float sscale = 0.125f * LOG2E;   // softmax in exp2 domain

    const int ntiles = S_LEN / 64;
    for (int t = 0; t < ntiles; t++) {
        if (t == ntiles - 1) { CP_WAIT0; } else { CP_WAIT1; }
        __syncthreads();
        const uint32_t stg = sb + (t & 1) * AT_STSZ;

        // --- scores: 3-term split QK^T ---
        float s[8][4];
#pragma unroll
        for (int j = 0; j < 8; j++)
#pragma unroll
            for (int r = 0; r < 4; r++) s[j][r] = 0.f;
#pragma unroll
        for (int ks = 0; ks < 4; ks++) {
#pragma unroll
            for (int jg = 0; jg < 4; jg++) {
                uint32_t kh[4], kl[4];
                ldsm_x4(kh[0], kh[1], kh[2], kh[3], stg +        sw128(boffA[jg] + ks * 32));
                ldsm_x4(kl[0], kl[1], kl[2], kl[3], stg + 8192 + sw128(boffA[jg] + ks * 32));
                const int j0 = 2 * jg, j1 = 2 * jg + 1;
                mma_bf16(s[j0], qh[ks][0], qh[ks][1], qh[ks][2], qh[ks][3], kh[0], kh[1]);
                mma_bf16(s[j1], qh[ks][0], qh[ks][1], qh[ks][2], qh[ks][3], kh[2], kh[3]);
                mma_bf16(s[j0], qh[ks][0], qh[ks][1], qh[ks][2], qh[ks][3], kl[0], kl[1]);
                mma_bf16(s[j1], qh[ks][0], qh[ks][1], qh[ks][2], qh[ks][3], kl[2], kl[3]);
                mma_bf16(s[j0], ql[ks][0], ql[ks][1], ql[ks][2], ql[ks][3], kh[0], kh[1]);
                mma_bf16(s[j1], ql[ks][0], ql[ks][1], ql[ks][2], ql[ks][3], kh[2], kh[3]);
            }
        }
        // --- scale (exp2 domain) + mask ---
        const float* madd = (const float*)(smem + AT_MASK + (t & 1) * 256);
#pragma unroll
        for (int j = 0; j < 8; j++) {
            const int c0 = j * 8 + (lane & 3) * 2;
            const float ma = madd[c0], mb = madd[c0 + 1];
            s[j][0] = s[j][0] * sscale + ma;
            s[j][1] = s[j][1] * sscale + mb;
            s[j][2] = s[j][2] * sscale + ma;
            s[j][3] = s[j][3] * sscale + mb;
        }
        // --- online softmax (2 rows per thread, exp2 domain) ---
        float mx0 = s[0][0], mx1 = s[0][2];
#pragma unroll
        for (int j = 0; j < 8; j++) {
            mx0 = fmaxf(mx0, fmaxf(s[j][0], s[j][1]));
            mx1 = fmaxf(mx1, fmaxf(s[j][2], s[j][3]));
        }
        mx0 = fmaxf(mx0, __shfl_xor_sync(0xffffffff, mx0, 1));
        mx0 = fmaxf(mx0, __shfl_xor_sync(0xffffffff, mx0, 2));
        mx1 = fmaxf(mx1, __shfl_xor_sync(0xffffffff, mx1, 1));
        mx1 = fmaxf(mx1, __shfl_xor_sync(0xffffffff, mx1, 2));
        const float mn0 = fmaxf(m0, mx0), mn1 = fmaxf(m1, mx1);
        const float cr0 = ex2(m0 - mn0), cr1 = ex2(m1 - mn1);
        m0 = mn0; m1 = mn1; l0 *= cr0; l1 *= cr1;
#pragma unroll
        for (int j = 0; j < 8; j++) {
            o[j][0] *= cr0; o[j][1] *= cr0; o[j][2] *= cr1; o[j][3] *= cr1;
            s[j][0] = ex2(s[j][0] - m0);
            s[j][1] = ex2(s[j][1] - m0);
            s[j][2] = ex2(s[j][2] - m1);
            s[j][3] = ex2(s[j][3] - m1);
            l0 += s[j][0] + s[j][1];
            l1 += s[j][2] + s[j][3];
        }
        // --- PV: 3-term split; V fragments via trans ldmatrix ---
#pragma unroll
        for (int kk = 0; kk < 4; kk++) {
            uint32_t ph[4], pl[4];
            split2(s[2 * kk][0],     s[2 * kk][1],     ph[0], pl[0]);
            split2(s[2 * kk][2],     s[2 * kk][3],     ph[1], pl[1]);
            split2(s[2 * kk + 1][0], s[2 * kk + 1][1], ph[2], pl[2]);
            split2(s[2 * kk + 1][2], s[2 * kk + 1][3], ph[3], pl[3]);
            const uint32_t vk = vbase + (uint32_t)(kk * 16 * 128);
#pragma unroll
            for (int jg = 0; jg < 4; jg++) {
                uint32_t vh[4], vl[4];
                ldsm_x4_t(vh[0], vh[1], vh[2], vh[3], stg + 16384 + sw128(vk + jg * 32));
                ldsm_x4_t(vl[0], vl[1], vl[2], vl[3], stg + 24576 + sw128(vk + jg * 32));
                const int j0 = 2 * jg, j1 = 2 * jg + 1;
                mma_bf16(o[j0], ph[0], ph[1], ph[2], ph[3], vh[0], vh[1]);
                mma_bf16(o[j1], ph[0], ph[1], ph[2], ph[3], vh[2], vh[3]);
                mma_bf16(o[j0], pl[0], pl[1], pl[2], pl[3], vh[0], vh[1]);
                mma_bf16(o[j1], pl[0], pl[1], pl[2], pl[3], vh[2], vh[3]);
                mma_bf16(o[j0], ph[0], ph[1], ph[2], ph[3], vl[0], vl[1]);
                mma_bf16(o[j1], ph[0], ph[1], ph[2], ph[3], vl[2], vl[3]);
            }
        }
        __syncthreads();
        if (t + 2 < ntiles) issue(t + 2);
    }

    // ---- finalize ----
    l0 += __shfl_xor_sync(0xffffffff, l0, 1);
    l0 += __shfl_xor_sync(0xffffffff, l0, 2);
    l1 += __shfl_xor_sync(0xffffffff, l1, 1);
    l1 += __shfl_xor_sync(0xffffffff, l1, 2);
    const float inv0 = 1.f / l0, inv1 = 1.f / l1;
    const size_t gr0 = (size_t)(b * S_LEN + q0 + wid * 16 + (lane >> 2));
    const size_t gr1 = gr0 + 8;
#pragma unroll
    for (int j = 0; j < 8; j++) {
        const int col = h * 64 + j * 8 + (lane & 3) * 2;
        uint32_t hh, ll;
        split2(o[j][0] * inv0, o[j][1] * inv0, hh, ll);
        *(uint32_t*)(ctxhi + gr0 * D_DIM + col) = hh;
        *(uint32_t*)(ctxlo + gr0 * D_DIM + col) = ll;
        split2(o[j][2] * inv1, o[j][3] * inv1, hh, ll);
        *(uint32_t*)(ctxhi + gr1 * D_DIM + col) = hh;
        *(uint32_t*)(ctxlo + gr1 * D_DIM + col) = ll;
    }
}

// ---------------- LayerNorm (warp-shuffle reduce), optional split --------
template<bool SPLIT>
__global__ __launch_bounds__(256)
void ln_kernel(const float* __restrict__ x, const float* __restrict__ g,
               const float* __restrict__ be, float* __restrict__ out,
               __nv_bfloat16* __restrict__ ohi, __nv_bfloat16* __restrict__ olo)
{
    __shared__ float red[8];
    __shared__ float red2[8];
    const int row = blockIdx.x;
    const int tid = threadIdx.x;
    const int lane = tid & 31;
    const int wid  = tid >> 5;

    float4 xv = ((const float4*)(x + (size_t)row * D_DIM))[tid];
    float s = (xv.x + xv.y) + (xv.z + xv.w);
#pragma unroll
    for (int off = 16; off > 0; off >>= 1) s += __shfl_xor_sync(0xffffffff, s, off);
    if (lane == 0) red[wid] = s;
    __syncthreads();
    float tot = red[0];
#pragma unroll
    for (int w = 1; w < 8; w++) tot += red[w];
    const float mean = tot * (1.f / (float)D_DIM);

    float dx0 = xv.x - mean, dx1 = xv.y - mean, dx2 = xv.z - mean, dx3 = xv.w - mean;
    float v = (dx0 * dx0 + dx1 * dx1) + (dx2 * dx2 + dx3 * dx3);
#pragma unroll
    for (int off = 16; off > 0; off >>= 1) v += __shfl_xor_sync(0xffffffff, v, off);
    if (lane == 0) red2[wid] = v;
    __syncthreads();
    float vtot = red2[0];
#pragma unroll
    for (int w = 1; w < 8; w++) vtot += red2[w];
    const float var  = vtot * (1.f / (float)(D_DIM - 1));
    const float istd = 1.f / (sqrtf(var) + 1e-6f);

    float4 gv  = ((const float4*)g)[tid];
    float4 bev = ((const float4*)be)[tid];
    float4 oo;
    oo.x = gv.x * dx0 * istd + bev.x;
    oo.y = gv.y * dx1 * istd + bev.y;
    oo.z = gv.z * dx2 * istd + bev.z;
    oo.w = gv.w * dx3 * istd + bev.w;
    ((float4*)(out + (size_t)row * D_DIM))[tid] = oo;
    if (SPLIT) {
        uint32_t h0, l0, h1, l1;
        split2(oo.x, oo.y, h0, l0);
        split2(oo.z, oo.w, h1, l1);
        ((uint2*)(ohi + (size_t)row * D_DIM))[tid] = make_uint2(h0, h1);
        ((uint2*)(olo + (size_t)row * D_DIM))[tid] = make_uint2(l0, l1);
    }
}

// ---------------- host launcher -----------------------------------------
extern "C" void kernel_launch(void* const* d_in, const int* in_sizes, int n_in,
                              void* d_out, int out_size)
{
    const float* x    = (const float*)d_in[0];
    const int*   mask = (const int*)  d_in[1];
    const float* Wq   = (const float*)d_in[2];
    const float* bq   = (const float*)d_in[3];
    const float* Wk   = (const float*)d_in[4];
    const float* bk   = (const float*)d_in[5];
    const float* Wv   = (const float*)d_in[6];
    const float* bv   = (const float*)d_in[7];
    const float* Wo   = (const float*)d_in[8];
    const float* bo   = (const float*)d_in[9];
    const float* W1   = (const float*)d_in[10];
    const float* b1   = (const float*)d_in[11];
    const float* W2   = (const float*)d_in[12];
    const float* b2   = (const float*)d_in[13];
    const float* g1   = (const float*)d_in[14];
    const float* be1  = (const float*)d_in[15];
    const float* g2   = (const float*)d_in[16];
    const float* be2  = (const float*)d_in[17];
    float* out = (float*)d_out;

    __nv_bfloat16 *xhi, *xlo, *wqkvhi, *wqkvlo, *wohi, *wolo, *w1hi, *w1lo, *w2hi, *w2lo;
    __nv_bfloat16 *qkvhi, *qkvlo, *ctxhi, *ctxlo, *x1hi, *x1lo, *hhi, *hlo;
    float *bqkv, *y1, *x1f, *y2;
    cudaGetSymbolAddress((void**)&xhi, g_xhi);       cudaGetSymbolAddress((void**)&xlo, g_xlo);
    cudaGetSymbolAddress((void**)&wqkvhi, g_wqkvhi); cudaGetSymbolAddress((void**)&wqkvlo, g_wqkvlo);
    cudaGetSymbolAddress((void**)&wohi, g_wohi);     cudaGetSymbolAddress((void**)&wolo, g_wolo);
    cudaGetSymbolAddress((void**)&w1hi, g_w1hi);     cudaGetSymbolAddress((void**)&w1lo, g_w1lo);
    cudaGetSymbolAddress((void**)&w2hi, g_w2hi);     cudaGetSymbolAddress((void**)&w2lo, g_w2lo);
    cudaGetSymbolAddress((void**)&bqkv, g_bqkv);
    cudaGetSymbolAddress((void**)&qkvhi, g_qkvhi);   cudaGetSymbolAddress((void**)&qkvlo, g_qkvlo);
    cudaGetSymbolAddress((void**)&ctxhi, g_ctxhi);   cudaGetSymbolAddress((void**)&ctxlo, g_ctxlo);
    cudaGetSymbolAddress((void**)&x1hi, g_x1hi);     cudaGetSymbolAddress((void**)&x1lo, g_x1lo);
    cudaGetSymbolAddress((void**)&hhi, g_hhi);       cudaGetSymbolAddress((void**)&hlo, g_hlo);
    cudaGetSymbolAddress((void**)&y1, g_y1);
    cudaGetSymbolAddress((void**)&x1f, g_x1f);
    cudaGetSymbolAddress((void**)&y2, g_y2);

    cudaFuncSetAttribute(hmma_gemm2<0, false, true >, cudaFuncAttributeMaxDynamicSharedMemorySize, GEMM_SMEM);
    cudaFuncSetAttribute(hmma_gemm2<1, false, false>, cudaFuncAttributeMaxDynamicSharedMemorySize, GEMM_SMEM);
    cudaFuncSetAttribute(hmma_gemm2<1, true,  false>, cudaFuncAttributeMaxDynamicSharedMemorySize, GEMM_SMEM);
    cudaFuncSetAttribute(attn_mma, cudaFuncAttributeMaxDynamicSharedMemorySize, AT_SMEM);

    // ---- conversions (weights + x + bias concat): ONE launch ----
    convsplit8<<<dim3(296, 8), 256>>>(
        x,  xhi, xlo, M_ROWS * D_DIM / 4,
        Wq, wqkvhi,                     wqkvlo,                     D_DIM * D_DIM / 4,
        Wk, wqkvhi + D_DIM * D_DIM,     wqkvlo + D_DIM * D_DIM,     D_DIM * D_DIM / 4,
        Wv, wqkvhi + 2 * D_DIM * D_DIM, wqkvlo + 2 * D_DIM * D_DIM, D_DIM * D_DIM / 4,
        Wo, wohi, wolo, D_DIM * D_DIM / 4,
        W1, w1hi, w1lo, DFF_D * D_DIM / 4,
        W2, w2hi, w2lo, D_DIM * DFF_D / 4,
        bq, bk, bv, bqkv);

    // ---- fused QKV projection (split output) ----
    hmma_gemm2<1, false, false><<<dim3(3 * D_DIM / 128, M_ROWS / 128), 256, GEMM_SMEM>>>(
        xhi, xlo, wqkvhi, wqkvlo, bqkv, nullptr, nullptr, qkvhi, qkvlo, M_ROWS, 3 * D_DIM, D_DIM);

    // ---- attention (64-q tiles, 128 threads, 3 CTA/SM, V via trans-ldsm) ----
    attn_mma<<<dim3(S_LEN / 64, B_SZ * NHEAD), 128, AT_SMEM>>>(
        qkvhi, qkvlo, mask, ctxhi, ctxlo);

    // ---- O projection + residual, LN1 (emits split) ----
    hmma_gemm2<0, false, true><<<dim3(D_DIM / 128, M_ROWS / 128), 256, GEMM_SMEM>>>(
        ctxhi, ctxlo, wohi, wolo, bo, x, y1, nullptr, nullptr, M_ROWS, D_DIM, D_DIM);
    ln_kernel<true><<<M_ROWS, 256>>>(y1, g1, be1, x1f, x1hi, x1lo);

    // ---- FFN ----
    hmma_gemm2<1, true, false><<<dim3(DFF_D / 128, M_ROWS / 128), 256, GEMM_SMEM>>>(
        x1hi, x1lo, w1hi, w1lo, b1, nullptr, nullptr, hhi, hlo, M_ROWS, DFF_D, D_DIM);
    hmma_gemm2<0, false, true><<<dim3(D_DIM / 128, M_ROWS / 128), 256, GEMM_SMEM>>>(
        hhi, hlo, w2hi, w2lo, b2, x1f, y2, nullptr, nullptr, M_ROWS, D_DIM, DFF_D);
    ln_kernel<false><<<M_ROWS, 256>>>(y2, g2, be2, out, nullptr, nullptr);
}

// round 15
// speedup vs baseline: 1.0262x; 1.0262x over previous
#include <cuda_runtime.h>
#include <cuda_bf16.h>
#include <cstdint>
#include <math.h>

// Problem dims (fixed)
#define B_SZ   4
#define S_LEN  2048
#define D_DIM  1024
#define NHEAD  16
#define DFF_D  4096
#define M_ROWS 8192   // B*S
#define LOG2E  1.4426950408889634f

// ---------------- scratch (static __device__; no allocation) --------------
__device__ __nv_bfloat16 g_xhi [M_ROWS * D_DIM], g_xlo [M_ROWS * D_DIM];
__device__ __nv_bfloat16 g_wqkvhi[3 * D_DIM * D_DIM], g_wqkvlo[3 * D_DIM * D_DIM];
__device__ __nv_bfloat16 g_wohi[D_DIM * D_DIM], g_wolo[D_DIM * D_DIM];
__device__ __nv_bfloat16 g_w1hi[DFF_D * D_DIM], g_w1lo[DFF_D * D_DIM];
__device__ __nv_bfloat16 g_w2hi[D_DIM * DFF_D], g_w2lo[D_DIM * DFF_D];
__device__ float         g_bqkv[3 * D_DIM];
__device__ __nv_bfloat16 g_qkvhi[(size_t)M_ROWS * 3 * D_DIM], g_qkvlo[(size_t)M_ROWS * 3 * D_DIM];
__device__ __nv_bfloat16 g_ctxhi[M_ROWS * D_DIM], g_ctxlo[M_ROWS * D_DIM];
__device__ float         g_y1 [M_ROWS * D_DIM], g_x1f[M_ROWS * D_DIM], g_y2[M_ROWS * D_DIM];
__device__ __nv_bfloat16 g_x1hi[M_ROWS * D_DIM], g_x1lo[M_ROWS * D_DIM];
__device__ __nv_bfloat16 g_hhi[(size_t)M_ROWS * DFF_D], g_hlo[(size_t)M_ROWS * DFF_D];

// ======================= helpers ==========================================
__device__ __forceinline__ uint32_t smem_u32(const void* p) {
    uint32_t a;
    asm("{ .reg .u64 t; cvta.to.shared.u64 t, %1; cvt.u32.u64 %0, t; }" : "=r"(a) : "l"(p));
    return a;
}
__device__ __forceinline__ uint32_t sw128(uint32_t off) { return off ^ ((off >> 3) & 0x70); }
__device__ __forceinline__ uint32_t sw64 (uint32_t off) { return off ^ ((off >> 3) & 0x30); }

__device__ __forceinline__ void ldsm_x4(uint32_t& r0, uint32_t& r1, uint32_t& r2, uint32_t& r3,
                                        uint32_t addr) {
    asm volatile("ldmatrix.sync.aligned.m8n8.x4.shared.b16 {%0,%1,%2,%3}, [%4];"
                 : "=r"(r0), "=r"(r1), "=r"(r2), "=r"(r3) : "r"(addr));
}
__device__ __forceinline__ void ldsm_x4_t(uint32_t& r0, uint32_t& r1, uint32_t& r2, uint32_t& r3,
                                          uint32_t addr) {
    asm volatile("ldmatrix.sync.aligned.m8n8.x4.trans.shared.b16 {%0,%1,%2,%3}, [%4];"
                 : "=r"(r0), "=r"(r1), "=r"(r2), "=r"(r3) : "r"(addr));
}
__device__ __forceinline__ void mma_bf16(float* d, uint32_t a0, uint32_t a1, uint32_t a2,
                                         uint32_t a3, uint32_t b0, uint32_t b1) {
    asm volatile(
        "mma.sync.aligned.m16n8k16.row.col.f32.bf16.bf16.f32 "
        "{%0,%1,%2,%3}, {%4,%5,%6,%7}, {%8,%9}, {%0,%1,%2,%3};"
        : "+f"(d[0]), "+f"(d[1]), "+f"(d[2]), "+f"(d[3])
        : "r"(a0), "r"(a1), "r"(a2), "r"(a3), "r"(b0), "r"(b1));
}
// split pair (a=elem0/lo, b=elem1/hi) into hi/lo bf16x2
__device__ __forceinline__ void split2(float a, float b, uint32_t& hi, uint32_t& lo) {
    uint32_t h;
    asm("cvt.rn.bf16x2.f32 %0, %1, %2;" : "=r"(h) : "f"(b), "f"(a));
    float ra = a - __uint_as_float(h << 16);
    float rb = b - __uint_as_float(h & 0xffff0000u);
    uint32_t l;
    asm("cvt.rn.bf16x2.f32 %0, %1, %2;" : "=r"(l) : "f"(rb), "f"(ra));
    hi = h; lo = l;
}
__device__ __forceinline__ float ex2(float x) {
    float r;
    asm("ex2.approx.ftz.f32 %0, %1;" : "=f"(r) : "f"(x));
    return r;
}

#define CP_ASYNC16(dst, src) \
    asm volatile("cp.async.cg.shared.global [%0], [%1], 16;" :: "r"(dst), "l"(src))
#define CP_COMMIT asm volatile("cp.async.commit_group;" ::: "memory")
#define CP_WAIT1  asm volatile("cp.async.wait_group 1;" ::: "memory")
#define CP_WAIT0  asm volatile("cp.async.wait_group 0;" ::: "memory")

// ---------------- fused fp32 -> split bf16 conversion + bias concat -------
// blockIdx.y 0..6: split segments (MLP-4 batched); blockIdx.y 7: bias concat.
__global__ void convsplit8(
    const float* s0, __nv_bfloat16* h0, __nv_bfloat16* l0, int n0,
    const float* s1, __nv_bfloat16* h1, __nv_bfloat16* l1, int n1,
    const float* s2, __nv_bfloat16* h2, __nv_bfloat16* l2, int n2,
    const float* s3, __nv_bfloat16* h3, __nv_bfloat16* l3, int n3,
    const float* s4, __nv_bfloat16* h4, __nv_bfloat16* l4, int n4,
    const float* s5, __nv_bfloat16* h5, __nv_bfloat16* l5, int n5,
    const float* s6, __nv_bfloat16* h6, __nv_bfloat16* l6, int n6,
    const float* bq, const float* bk, const float* bv, float* bqkv)
{
    if (blockIdx.y == 7) {
        const int stride = gridDim.x * blockDim.x;
        for (int i = blockIdx.x * blockDim.x + threadIdx.x; i < 3 * D_DIM; i += stride)
            bqkv[i] = (i < D_DIM) ? bq[i]
                    : ((i < 2 * D_DIM) ? bk[i - D_DIM] : bv[i - 2 * D_DIM]);
        return;
    }
    const float* src; __nv_bfloat16 *hi, *lo; int n;
    switch (blockIdx.y) {
        case 0: src = s0; hi = h0; lo = l0; n = n0; break;
        case 1: src = s1; hi = h1; lo = l1; n = n1; break;
        case 2: src = s2; hi = h2; lo = l2; n = n2; break;
        case 3: src = s3; hi = h3; lo = l3; n = n3; break;
        case 4: src = s4; hi = h4; lo = l4; n = n4; break;
        case 5: src = s5; hi = h5; lo = l5; n = n5; break;
        default: src = s6; hi = h6; lo = l6; n = n6; break;
    }
    const int stride = gridDim.x * blockDim.x;
    const int base   = blockIdx.x * blockDim.x + threadIdx.x;
    // 4 independent float4 loads in flight per iteration (MLP=4)
    for (int i = base; i < n; i += stride * 4) {
        float4 v[4];
        int idx[4];
        bool ok[4];
#pragma unroll
        for (int u = 0; u < 4; u++) {
            idx[u] = i + u * stride;
            ok[u]  = idx[u] < n;
            if (ok[u]) v[u] = ((const float4*)src)[idx[u]];
        }
#pragma unroll
        for (int u = 0; u < 4; u++) {
            if (ok[u]) {
                uint32_t a0, b0, a1, b1;
                split2(v[u].x, v[u].y, a0, b0);
                split2(v[u].z, v[u].w, a1, b1);
                ((uint2*)hi)[idx[u]] = make_uint2(a0, a1);
                ((uint2*)lo)[idx[u]] = make_uint2(b0, b1);
            }
        }
    }
}

// ========== HMMA GEMM on pre-split inputs: C = A @ B^T + bias =============
// Tile 128x128, K-chunk 32 (64B SW64 rows), 3-stage cp.async, one sync per
// chunk, 2 CTAs/SM. (Round-13 verified inner loop.)
// MODE 0: fp32 out (+RES). MODE 1: split bf16 out (+RELU).
#define ST_A  0
#define ST_AL 8192
#define ST_B  16384
#define ST_BL 24576
#define ST_SZ 32768
#define GEMM_SMEM (3 * ST_SZ)

template<int MODE, bool RELU, bool RES>
__global__ __launch_bounds__(256, 2)
void hmma_gemm2(const __nv_bfloat16* __restrict__ Ahi, const __nv_bfloat16* __restrict__ Alo,
                const __nv_bfloat16* __restrict__ Bhi, const __nv_bfloat16* __restrict__ Blo,
                const float* __restrict__ bias, const float* __restrict__ Rp,
                float* __restrict__ Cf, __nv_bfloat16* __restrict__ Chi,
                __nv_bfloat16* __restrict__ Clo, int M, int N, int K)
{
    extern __shared__ __align__(1024) char smem[];
    const uint32_t sb = smem_u32(smem);
    const int tid  = threadIdx.x;
    const int lane = tid & 31;
    const int wid  = tid >> 5;
    const int wm   = wid & 3;
    const int wn   = wid >> 2;
    const int bx = blockIdx.x, by = blockIdx.y;

    const int lrow = tid >> 1;
    const int lc   = (tid & 1) * 2;
    const __nv_bfloat16* src0 = Ahi + (size_t)(by * 128 + lrow) * K;
    const __nv_bfloat16* src1 = Alo + (size_t)(by * 128 + lrow) * K;
    const __nv_bfloat16* src2 = Bhi + (size_t)(bx * 128 + lrow) * K;
    const __nv_bfloat16* src3 = Blo + (size_t)(bx * 128 + lrow) * K;
    uint32_t dsw[2];
#pragma unroll
    for (int ch = 0; ch < 2; ch++) dsw[ch] = sw64((uint32_t)(lrow * 64 + (lc + ch) * 16));

    const int nchunk = K >> 5;
    auto issue = [&](int c) {
        const uint32_t stg = sb + (uint32_t)(c % 3) * ST_SZ;
        const int ko = c * 32 + lc * 8;
#pragma unroll
        for (int ch = 0; ch < 2; ch++) {
            CP_ASYNC16(stg + ST_A  + dsw[ch], src0 + ko + ch * 8);
            CP_ASYNC16(stg + ST_AL + dsw[ch], src1 + ko + ch * 8);
            CP_ASYNC16(stg + ST_B  + dsw[ch], src2 + ko + ch * 8);
            CP_ASYNC16(stg + ST_BL + dsw[ch], src3 + ko + ch * 8);
        }
        CP_COMMIT;
    };

    uint32_t aoff[2];
    {
        const int m  = wm * 32 + (lane & 7) + 8 * ((lane >> 3) & 1);
        const int ak = (lane >> 4) * 16;
        aoff[0] = (uint32_t)(m * 64 + ak);
        aoff[1] = aoff[0] + 16 * 64;
    }
    uint32_t boff[4];
    {
        const int bk = ((lane >> 3) & 1) * 16;
#pragma unroll
        for (int jg = 0; jg < 4; jg++) {
            const int n = wn * 64 + jg * 16 + (lane & 7) + 8 * (lane >> 4);
            boff[jg] = (uint32_t)(n * 64 + bk);
        }
    }

    float acc[2][8][4];
#pragma unroll
    for (int i = 0; i < 2; i++)
#pragma unroll
        for (int j = 0; j < 8; j++)
#pragma unroll
            for (int r = 0; r < 4; r++) acc[i][j][r] = 0.f;

    issue(0);
    issue(1);

    for (int c = 0; c < nchunk; c++) {
        if (c == nchunk - 1) { CP_WAIT0; } else { CP_WAIT1; }
        __syncthreads();
        if (c + 2 < nchunk) issue(c + 2);
        const uint32_t bufb = sb + (uint32_t)(c % 3) * ST_SZ;
#pragma unroll
        for (int ks = 0; ks < 2; ks++) {
            const uint32_t o = ks * 32;
            uint32_t ah0[4], ah1[4], al0[4], al1[4];
            ldsm_x4(ah0[0], ah0[1], ah0[2], ah0[3], bufb + ST_A  + sw64(aoff[0] + o));
            ldsm_x4(ah1[0], ah1[1], ah1[2], ah1[3], bufb + ST_A  + sw64(aoff[1] + o));
            ldsm_x4(al0[0], al0[1], al0[2], al0[3], bufb + ST_AL + sw64(aoff[0] + o));
            ldsm_x4(al1[0], al1[1], al1[2], al1[3], bufb + ST_AL + sw64(aoff[1] + o));
#pragma unroll
            for (int jg = 0; jg < 4; jg++) {
                uint32_t bh[4], bl[4];
                ldsm_x4(bh[0], bh[1], bh[2], bh[3], bufb + ST_B  + sw64(boff[jg] + o));
                ldsm_x4(bl[0], bl[1], bl[2], bl[3], bufb + ST_BL + sw64(boff[jg] + o));
                const int j0 = 2 * jg, j1 = 2 * jg + 1;
                mma_bf16(acc[0][j0], ah0[0], ah0[1], ah0[2], ah0[3], bh[0], bh[1]);
                mma_bf16(acc[0][j1], ah0[0], ah0[1], ah0[2], ah0[3], bh[2], bh[3]);
                mma_bf16(acc[1][j0], ah1[0], ah1[1], ah1[2], ah1[3], bh[0], bh[1]);
                mma_bf16(acc[1][j1], ah1[0], ah1[1], ah1[2], ah1[3], bh[2], bh[3]);
                mma_bf16(acc[0][j0], ah0[0], ah0[1], ah0[2], ah0[3], bl[0], bl[1]);
                mma_bf16(acc[0][j1], ah0[0], ah0[1], ah0[2], ah0[3], bl[2], bl[3]);
                mma_bf16(acc[1][j0], ah1[0], ah1[1], ah1[2], ah1[3], bl[0], bl[1]);
                mma_bf16(acc[1][j1], ah1[0], ah1[1], ah1[2], ah1[3], bl[2], bl[3]);
                mma_bf16(acc[0][j0], al0[0], al0[1], al0[2], al0[3], bh[0], bh[1]);
                mma_bf16(acc[0][j1], al0[0], al0[1], al0[2], al0[3], bh[2], bh[3]);
                mma_bf16(acc[1][j0], al1[0], al1[1], al1[2], al1[3], bh[0], bh[1]);
                mma_bf16(acc[1][j1], al1[0], al1[1], al1[2], al1[3], bh[2], bh[3]);
            }
        }
    }

    // epilogue: fragment row = lane>>2 (+8), col = (lane&3)*2
    const int rbase = by * 128 + wm * 32 + (lane >> 2);
    const int cbase = bx * 128 + wn * 64 + (lane & 3) * 2;
#pragma unroll
    for (int i = 0; i < 2; i++) {
#pragma unroll
        for (int j = 0; j < 8; j++) {
            const int r0 = rbase + i * 16;
            const int cc = cbase + j * 8;
            const float2 bv = *(const float2*)&bias[cc];
            float2 v0, v1;
            v0.x = acc[i][j][0] + bv.x;  v0.y = acc[i][j][1] + bv.y;
            v1.x = acc[i][j][2] + bv.x;  v1.y = acc[i][j][3] + bv.y;
            if (RES) {
                float2 q0 = *(const float2*)&Rp[(size_t)r0 * N + cc];
                float2 q1 = *(const float2*)&Rp[(size_t)(r0 + 8) * N + cc];
                v0.x += q0.x; v0.y += q0.y; v1.x += q1.x; v1.y += q1.y;
            }
            if (RELU) {
                v0.x = fmaxf(v0.x, 0.f); v0.y = fmaxf(v0.y, 0.f);
                v1.x = fmaxf(v1.x, 0.f); v1.y = fmaxf(v1.y, 0.f);
            }
            if (MODE == 0) {
                *(float2*)&Cf[(size_t)r0 * N + cc]       = v0;
                *(float2*)&Cf[(size_t)(r0 + 8) * N + cc] = v1;
            } else {
                uint32_t h, l;
                split2(v0.x, v0.y, h, l);
                *(uint32_t*)(Chi + (size_t)r0 * N + cc) = h;
                *(uint32_t*)(Clo + (size_t)r0 * N + cc) = l;
                split2(v1.x, v1.y, h, l);
                *(uint32_t*)(Chi + (size_t)(r0 + 8) * N + cc) = h;
                *(uint32_t*)(Clo + (size_t)(r0 + 8) * N + cc) = l;
            }
        }
    }
}

// ---------------- HMMA flash attention (64q, 128 threads, 3 CTA/SM) ------
// V consumed straight from qkv layout [key, d] via ldmatrix.trans (no vtrans).
// Q staging region is overlapped by the K/V stage buffers.
#define AT_STSZ  32768        // KHI 8K | KLO 8K | VHI 8K | VLO 8K
#define AT_MASK  (2 * AT_STSZ)
#define AT_SMEM  (AT_MASK + 2 * 256 + 256)

__global__ __launch_bounds__(128, 3)
void attn_mma(const __nv_bfloat16* __restrict__ qkvhi, const __nv_bfloat16* __restrict__ qkvlo,
              const int* __restrict__ mask,
              __nv_bfloat16* __restrict__ ctxhi, __nv_bfloat16* __restrict__ ctxlo)
{
    extern __shared__ __align__(1024) char smem[];
    const uint32_t sb = smem_u32(smem);
    const int tid  = threadIdx.x;
    const int lane = tid & 31;
    const int wid  = tid >> 5;
    const int q0   = blockIdx.x * 64;
    const int bh   = blockIdx.y;
    const int b    = bh >> 4, h = bh & 15;

    // ---- load Q tile (hi at 0, lo at 8192) into smem (overlaps stage 0) ----
#pragma unroll
    for (int it = 0; it < 4; it++) {
        const int idx = it * 128 + tid;
        const int row = idx >> 3, ch = idx & 7;
        const size_t src = (size_t)(b * S_LEN + q0 + row) * 3072 + h * 64 + ch * 8;
        const uint32_t d = sw128((uint32_t)(row * 128 + ch * 16));
        *(uint4*)(smem + d)        = *(const uint4*)(qkvhi + src);
        *(uint4*)(smem + 8192 + d) = *(const uint4*)(qkvlo + src);
    }

    // ldmatrix offset bases
    uint32_t qoffb;
    {
        const int m  = wid * 16 + (lane & 7) + 8 * ((lane >> 3) & 1);
        const int ak = (lane >> 4) * 16;
        qoffb = (uint32_t)(m * 128 + ak);
    }
    uint32_t boffA[4];     // K fragments (non-trans): rows=n(keys), cols=k bytes
    {
        const int bk = ((lane >> 3) & 1) * 16;
#pragma unroll
        for (int jg = 0; jg < 4; jg++) {
            const int n = jg * 16 + (lane & 7) + 8 * (lane >> 4);
            boffA[jg] = (uint32_t)(n * 128 + bk);
        }
    }
    // V trans-fragment base: rows=k(keys), cols=n(d) bytes
    const uint32_t vbase = (uint32_t)(((lane & 7) + 8 * ((lane >> 3) & 1)) * 128
                                      + (lane >> 4) * 16);

    __syncthreads();   // Q smem visible
    uint32_t qh[4][4], ql[4][4];
#pragma unroll
    for (int ks = 0; ks < 4; ks++) {
        ldsm_x4(qh[ks][0], qh[ks][1], qh[ks][2], qh[ks][3], sb +        sw128(qoffb + ks * 32));
        ldsm_x4(ql[ks][0], ql[ks][1], ql[ks][2], ql[ks][3], sb + 8192 + sw128(qoffb + ks * 32));
    }
    __syncthreads();   // all warps done reading Q before stages overwrite it

    auto issue = [&](int t) {
        const uint32_t stg = sb + (t & 1) * AT_STSZ;
        const int kt = t * 64;
#pragma unroll
        for (int it = 0; it < 4; it++) {
            const int idx = it * 128 + tid;
            const int row = idx >> 3, ch = idx & 7;
            const uint32_t d = sw128((uint32_t)(row * 128 + ch * 16));
            const size_t ksrc = (size_t)(b * S_LEN + kt + row) * 3072 + 1024 + h * 64 + ch * 8;
            CP_ASYNC16(stg +         d, qkvhi + ksrc);
            CP_ASYNC16(stg +  8192 + d, qkvlo + ksrc);
            CP_ASYNC16(stg + 16384 + d, qkvhi + ksrc + 1024);   // V cols [2048..3072)
            CP_ASYNC16(stg + 24576 + d, qkvlo + ksrc + 1024);
        }
        CP_COMMIT;
        if (tid < 64) {
            float* mp = (float*)(smem + AT_MASK + (t & 1) * 256);
            mp[tid] = mask[b * S_LEN + kt + tid] ? 0.f : -1e9f;
        }
    };

    issue(0);
    issue(1);

    float o[8][4];
#pragma unroll
    for (int j = 0; j < 8; j++)
#pragma unroll
        for (int r = 0; r < 4; r++) o[j][r] = 0.f;
    float m0 = -1e30f, m1 = -1e30f, l0 = 0.f, l1 = 0.f;
    const float sscale = 0.125f * LOG2E;   // softmax in exp2 domain

    const int ntiles = S_LEN / 64;
    for (int t = 0; t < ntiles; t++) {
        if (t == ntiles - 1) { CP_WAIT0; } else { CP_WAIT1; }
        __syncthreads();
        const uint32_t stg = sb + (t & 1) * AT_STSZ;

        // --- scores: 3-term split QK^T ---
        float s[8][4];
#pragma unroll
        for (int j = 0; j < 8; j++)
#pragma unroll
            for (int r = 0; r < 4; r++) s[j][r] = 0.f;
#pragma unroll
        for (int ks = 0; ks < 4; ks++) {
#pragma unroll
            for (int jg = 0; jg < 4; jg++) {
                uint32_t kh[4], kl[4];
                ldsm_x4(kh[0], kh[1], kh[2], kh[3], stg +        sw128(boffA[jg] + ks * 32));
                ldsm_x4(kl[0], kl[1], kl[2], kl[3], stg + 8192 + sw128(boffA[jg] + ks * 32));
                const int j0 = 2 * jg, j1 = 2 * jg + 1;
                mma_bf16(s[j0], qh[ks][0], qh[ks][1], qh[ks][2], qh[ks][3], kh[0], kh[1]);
                mma_bf16(s[j1], qh[ks][0], qh[ks][1], qh[ks][2], qh[ks][3], kh[2], kh[3]);
                mma_bf16(s[j0], qh[ks][0], qh[ks][1], qh[ks][2], qh[ks][3], kl[0], kl[1]);
                mma_bf16(s[j1], qh[ks][0], qh[ks][1], qh[ks][2], qh[ks][3], kl[2], kl[3]);
                mma_bf16(s[j0], ql[ks][0], ql[ks][1], ql[ks][2], ql[ks][3], kh[0], kh[1]);
                mma_bf16(s[j1], ql[ks][0], ql[ks][1], ql[ks][2], ql[ks][3], kh[2], kh[3]);
            }
        }
        // --- scale (exp2 domain) + mask ---
        const float* madd = (const float*)(smem + AT_MASK + (t & 1) * 256);
#pragma unroll
        for (int j = 0; j < 8; j++) {
            const int c0 = j * 8 + (lane & 3) * 2;
            const float ma = madd[c0], mb = madd[c0 + 1];
            s[j][0] = s[j][0] * sscale + ma;
            s[j][1] = s[j][1] * sscale + mb;
            s[j][2] = s[j][2] * sscale + ma;
            s[j][3] = s[j][3] * sscale + mb;
        }
        // --- online softmax (2 rows per thread, exp2 domain) ---
        float mx0 = s[0][0], mx1 = s[0][2];
#pragma unroll
        for (int j = 0; j < 8; j++) {
            mx0 = fmaxf(mx0, fmaxf(s[j][0], s[j][1]));
            mx1 = fmaxf(mx1, fmaxf(s[j][2], s[j][3]));
        }
        mx0 = fmaxf(mx0, __shfl_xor_sync(0xffffffff, mx0, 1));
        mx0 = fmaxf(mx0, __shfl_xor_sync(0xffffffff, mx0, 2));
        mx1 = fmaxf(mx1, __shfl_xor_sync(0xffffffff, mx1, 1));
        mx1 = fmaxf(mx1, __shfl_xor_sync(0xffffffff, mx1, 2));
        const float mn0 = fmaxf(m0, mx0), mn1 = fmaxf(m1, mx1);
        const float cr0 = ex2(m0 - mn0), cr1 = ex2(m1 - mn1);
        m0 = mn0; m1 = mn1; l0 *= cr0; l1 *= cr1;
#pragma unroll
        for (int j = 0; j < 8; j++) {
            o[j][0] *= cr0; o[j][1] *= cr0; o[j][2] *= cr1; o[j][3] *= cr1;
            s[j][0] = ex2(s[j][0] - m0);
            s[j][1] = ex2(s[j][1] - m0);
            s[j][2] = ex2(s[j][2] - m1);
            s[j][3] = ex2(s[j][3] - m1);
            l0 += s[j][0] + s[j][1];
            l1 += s[j][2] + s[j][3];
        }
        // --- PV: 3-term split; V fragments via trans ldmatrix ---
#pragma unroll
        for (int kk = 0; kk < 4; kk++) {
            uint32_t ph[4], pl[4];
            split2(s[2 * kk][0],     s[2 * kk][1],     ph[0], pl[0]);
            split2(s[2 * kk][2],     s[2 * kk][3],     ph[1], pl[1]);
            split2(s[2 * kk + 1][0], s[2 * kk + 1][1], ph[2], pl[2]);
            split2(s[2 * kk + 1][2], s[2 * kk + 1][3], ph[3], pl[3]);
            const uint32_t vk = vbase + (uint32_t)(kk * 16 * 128);
#pragma unroll
            for (int jg = 0; jg < 4; jg++) {
                uint32_t vh[4], vl[4];
                ldsm_x4_t(vh[0], vh[1], vh[2], vh[3], stg + 16384 + sw128(vk + jg * 32));
                ldsm_x4_t(vl[0], vl[1], vl[2], vl[3], stg + 24576 + sw128(vk + jg * 32));
                const int j0 = 2 * jg, j1 = 2 * jg + 1;
                mma_bf16(o[j0], ph[0], ph[1], ph[2], ph[3], vh[0], vh[1]);
                mma_bf16(o[j1], ph[0], ph[1], ph[2], ph[3], vh[2], vh[3]);
                mma_bf16(o[j0], pl[0], pl[1], pl[2], pl[3], vh[0], vh[1]);
                mma_bf16(o[j1], pl[0], pl[1], pl[2], pl[3], vh[2], vh[3]);
                mma_bf16(o[j0], ph[0], ph[1], ph[2], ph[3], vl[0], vl[1]);
                mma_bf16(o[j1], ph[0], ph[1], ph[2], ph[3], vl[2], vl[3]);
            }
        }
        __syncthreads();
        if (t + 2 < ntiles) issue(t + 2);
    }

    // ---- finalize ----
    l0 += __shfl_xor_sync(0xffffffff, l0, 1);
    l0 += __shfl_xor_sync(0xffffffff, l0, 2);
    l1 += __shfl_xor_sync(0xffffffff, l1, 1);
    l1 += __shfl_xor_sync(0xffffffff, l1, 2);
    const float inv0 = 1.f / l0, inv1 = 1.f / l1;
    const size_t gr0 = (size_t)(b * S_LEN + q0 + wid * 16 + (lane >> 2));
    const size_t gr1 = gr0 + 8;
#pragma unroll
    for (int j = 0; j < 8; j++) {
        const int col = h * 64 + j * 8 + (lane & 3) * 2;
        uint32_t hh, ll;
        split2(o[j][0] * inv0, o[j][1] * inv0, hh, ll);
        *(uint32_t*)(ctxhi + gr0 * D_DIM + col) = hh;
        *(uint32_t*)(ctxlo + gr0 * D_DIM + col) = ll;
        split2(o[j][2] * inv1, o[j][3] * inv1, hh, ll);
        *(uint32_t*)(ctxhi + gr1 * D_DIM + col) = hh;
        *(uint32_t*)(ctxlo + gr1 * D_DIM + col) = ll;
    }
}

// ---------------- LayerNorm (warp-shuffle reduce), optional split --------
template<bool SPLIT>
__global__ __launch_bounds__(256)
void ln_kernel(const float* __restrict__ x, const float* __restrict__ g,
               const float* __restrict__ be, float* __restrict__ out,
               __nv_bfloat16* __restrict__ ohi, __nv_bfloat16* __restrict__ olo)
{
    __shared__ float red[8];
    __shared__ float red2[8];
    const int row = blockIdx.x;
    const int tid = threadIdx.x;
    const int lane = tid & 31;
    const int wid  = tid >> 5;

    float4 xv = ((const float4*)(x + (size_t)row * D_DIM))[tid];
    float s = (xv.x + xv.y) + (xv.z + xv.w);
#pragma unroll
    for (int off = 16; off > 0; off >>= 1) s += __shfl_xor_sync(0xffffffff, s, off);
    if (lane == 0) red[wid] = s;
    __syncthreads();
    float tot = red[0];
#pragma unroll
    for (int w = 1; w < 8; w++) tot += red[w];
    const float mean = tot * (1.f / (float)D_DIM);

    float dx0 = xv.x - mean, dx1 = xv.y - mean, dx2 = xv.z - mean, dx3 = xv.w - mean;
    float v = (dx0 * dx0 + dx1 * dx1) + (dx2 * dx2 + dx3 * dx3);
#pragma unroll
    for (int off = 16; off > 0; off >>= 1) v += __shfl_xor_sync(0xffffffff, v, off);
    if (lane == 0) red2[wid] = v;
    __syncthreads();
    float vtot = red2[0];
#pragma unroll
    for (int w = 1; w < 8; w++) vtot += red2[w];
    const float var  = vtot * (1.f / (float)(D_DIM - 1));
    const float istd = 1.f / (sqrtf(var) + 1e-6f);

    float4 gv  = ((const float4*)g)[tid];
    float4 bev = ((const float4*)be)[tid];
    float4 oo;
    oo.x = gv.x * dx0 * istd + bev.x;
    oo.y = gv.y * dx1 * istd + bev.y;
    oo.z = gv.z * dx2 * istd + bev.z;
    oo.w = gv.w * dx3 * istd + bev.w;
    ((float4*)(out + (size_t)row * D_DIM))[tid] = oo;
    if (SPLIT) {
        uint32_t h0, l0, h1, l1;
        split2(oo.x, oo.y, h0, l0);
        split2(oo.z, oo.w, h1, l1);
        ((uint2*)(ohi + (size_t)row * D_DIM))[tid] = make_uint2(h0, h1);
        ((uint2*)(olo + (size_t)row * D_DIM))[tid] = make_uint2(l0, l1);
    }
}

// ---------------- host launcher -----------------------------------------
extern "C" void kernel_launch(void* const* d_in, const int* in_sizes, int n_in,
                              void* d_out, int out_size)
{
    const float* x    = (const float*)d_in[0];
    const int*   mask = (const int*)  d_in[1];
    const float* Wq   = (const float*)d_in[2];
    const float* bq   = (const float*)d_in[3];
    const float* Wk   = (const float*)d_in[4];
    const float* bk   = (const float*)d_in[5];
    const float* Wv   = (const float*)d_in[6];
    const float* bv   = (const float*)d_in[7];
    const float* Wo   = (const float*)d_in[8];
    const float* bo   = (const float*)d_in[9];
    const float* W1   = (const float*)d_in[10];
    const float* b1   = (const float*)d_in[11];
    const float* W2   = (const float*)d_in[12];
    const float* b2   = (const float*)d_in[13];
    const float* g1   = (const float*)d_in[14];
    const float* be1  = (const float*)d_in[15];
    const float* g2   = (const float*)d_in[16];
    const float* be2  = (const float*)d_in[17];
    float* out = (float*)d_out;

    __nv_bfloat16 *xhi, *xlo, *wqkvhi, *wqkvlo, *wohi, *wolo, *w1hi, *w1lo, *w2hi, *w2lo;
    __nv_bfloat16 *qkvhi, *qkvlo, *ctxhi, *ctxlo, *x1hi, *x1lo, *hhi, *hlo;
    float *bqkv, *y1, *x1f, *y2;
    cudaGetSymbolAddress((void**)&xhi, g_xhi);       cudaGetSymbolAddress((void**)&xlo, g_xlo);
    cudaGetSymbolAddress((void**)&wqkvhi, g_wqkvhi); cudaGetSymbolAddress((void**)&wqkvlo, g_wqkvlo);
    cudaGetSymbolAddress((void**)&wohi, g_wohi);     cudaGetSymbolAddress((void**)&wolo, g_wolo);
    cudaGetSymbolAddress((void**)&w1hi, g_w1hi);     cudaGetSymbolAddress((void**)&w1lo, g_w1lo);
    cudaGetSymbolAddress((void**)&w2hi, g_w2hi);     cudaGetSymbolAddress((void**)&w2lo, g_w2lo);
    cudaGetSymbolAddress((void**)&bqkv, g_bqkv);
    cudaGetSymbolAddress((void**)&qkvhi, g_qkvhi);   cudaGetSymbolAddress((void**)&qkvlo, g_qkvlo);
    cudaGetSymbolAddress((void**)&ctxhi, g_ctxhi);   cudaGetSymbolAddress((void**)&ctxlo, g_ctxlo);
    cudaGetSymbolAddress((void**)&x1hi, g_x1hi);     cudaGetSymbolAddress((void**)&x1lo, g_x1lo);
    cudaGetSymbolAddress((void**)&hhi, g_hhi);       cudaGetSymbolAddress((void**)&hlo, g_hlo);
    cudaGetSymbolAddress((void**)&y1, g_y1);
    cudaGetSymbolAddress((void**)&x1f, g_x1f);
    cudaGetSymbolAddress((void**)&y2, g_y2);

    cudaFuncSetAttribute(hmma_gemm2<0, false, true >, cudaFuncAttributeMaxDynamicSharedMemorySize, GEMM_SMEM);
    cudaFuncSetAttribute(hmma_gemm2<1, false, false>, cudaFuncAttributeMaxDynamicSharedMemorySize, GEMM_SMEM);
    cudaFuncSetAttribute(hmma_gemm2<1, true,  false>, cudaFuncAttributeMaxDynamicSharedMemorySize, GEMM_SMEM);
    cudaFuncSetAttribute(attn_mma, cudaFuncAttributeMaxDynamicSharedMemorySize, AT_SMEM);

    // ---- conversions (weights + x + bias concat): ONE launch ----
    convsplit8<<<dim3(296, 8), 256>>>(
        x,  xhi, xlo, M_ROWS * D_DIM / 4,
        Wq, wqkvhi,                     wqkvlo,                     D_DIM * D_DIM / 4,
        Wk, wqkvhi + D_DIM * D_DIM,     wqkvlo + D_DIM * D_DIM,     D_DIM * D_DIM / 4,
        Wv, wqkvhi + 2 * D_DIM * D_DIM, wqkvlo + 2 * D_DIM * D_DIM, D_DIM * D_DIM / 4,
        Wo, wohi, wolo, D_DIM * D_DIM / 4,
        W1, w1hi, w1lo, DFF_D * D_DIM / 4,
        W2, w2hi, w2lo, D_DIM * DFF_D / 4,
        bq, bk, bv, bqkv);

    // ---- fused QKV projection (split output) ----
    hmma_gemm2<1, false, false><<<dim3(3 * D_DIM / 128, M_ROWS / 128), 256, GEMM_SMEM>>>(
        xhi, xlo, wqkvhi, wqkvlo, bqkv, nullptr, nullptr, qkvhi, qkvlo, M_ROWS, 3 * D_DIM, D_DIM);

    // ---- attention (64-q tiles, 128 threads, 3 CTA/SM, V via trans-ldsm) ----
    attn_mma<<<dim3(S_LEN / 64, B_SZ * NHEAD), 128, AT_SMEM>>>(
        qkvhi, qkvlo, mask, ctxhi, ctxlo);

    // ---- O projection + residual, LN1 (emits split) ----
    hmma_gemm2<0, false, true><<<dim3(D_DIM / 128, M_ROWS / 128), 256, GEMM_SMEM>>>(
        ctxhi, ctxlo, wohi, wolo, bo, x, y1, nullptr, nullptr, M_ROWS, D_DIM, D_DIM);
    ln_kernel<true><<<M_ROWS, 256>>>(y1, g1, be1, x1f, x1hi, x1lo);

    // ---- FFN ----
    hmma_gemm2<1, true, false><<<dim3(DFF_D / 128, M_ROWS / 128), 256, GEMM_SMEM>>>(
        x1hi, x1lo, w1hi, w1lo, b1, nullptr, nullptr, hhi, hlo, M_ROWS, DFF_D, D_DIM);
    hmma_gemm2<0, false, true><<<dim3(D_DIM / 128, M_ROWS / 128), 256, GEMM_SMEM>>>(
        hhi, hlo, w2hi, w2lo, b2, x1f, y2, nullptr, nullptr, M_ROWS, D_DIM, DFF_D);
    ln_kernel<false><<<M_ROWS, 256>>>(y2, g2, be2, out, nullptr, nullptr);
}